// round 13
// baseline (speedup 1.0000x reference)
#include <cuda_runtime.h>
#include <cuda_fp16.h>
#include <cstdint>

// GCN 2-layer, CSR two-phase aggregation, sm_100a.
// f32x2 packed GEMM (2 rows/thread), Hs fp16, CSR agg with x8 MLP.
// Prep: zero-restore invariant kills k_init; hist/fill at 8 edges/thread.

#define N_NODES 100000
#define N_EDGES 1600000
#define D 64
#define FIXS 33554432.0f          // 2^25 fixed-point scale for weight sums
#define FIXR (1.0f / 33554432.0f)

__device__ unsigned long long g_pk[N_NODES];  // (cnt << 32) | fixed_weight_sum
__device__ float g_dis[N_NODES];        // rsqrt(degree)
__device__ int   g_cnt[N_NODES];        // in-degree (edges only)
__device__ int   g_row[N_NODES];        // CSR row start (bump-allocated)
__device__ int   g_total;               // bump allocator
__device__ int   g_pos[N_EDGES];        // within-bin slot (from hist atomic)
__device__ int2  g_bins[N_EDGES];       // (src, w-as-int), dst-binned
__device__ uint2 g_h[N_NODES * 16];     // Hs fp16: 64 half = 16 uint2 per node
__device__ float g_agg[N_NODES * D];    // layer-1 output (fp32)

// ---------------------------------------------------------------------------
// packed f32x2 helpers (sm_100+)
// ---------------------------------------------------------------------------
__device__ __forceinline__ unsigned long long bcast2(float x) {
    unsigned long long r;
    asm("mov.b64 %0, {%1, %1};" : "=l"(r) : "f"(x));
    return r;
}
__device__ __forceinline__ void fma2(unsigned long long& d,
                                     unsigned long long a,
                                     unsigned long long b) {
    asm("fma.rn.f32x2 %0, %1, %2, %0;" : "+l"(d) : "l"(a), "l"(b));
}
__device__ __forceinline__ float2 unpack2(unsigned long long v) {
    float2 f;
    asm("mov.b64 {%0, %1}, %2;" : "=f"(f.x), "=f"(f.y) : "l"(v));
    return f;
}

// ---------------------------------------------------------------------------
// hist: 8 edges/thread; packed 64-bit atomic: count(hi) + fix-point wsum(lo).
// Also resets g_total for this call (ordered before k_alloc by kernel bound).
// g_pk is zero on entry (zero-init at load; k_alloc restores after reading).
// ---------------------------------------------------------------------------
__global__ void k_hist(const int* __restrict__ dst,
                       const float* __restrict__ w) {
    int t = blockIdx.x * blockDim.x + threadIdx.x;
    if (t == 0) g_total = 0;
    if (t >= N_EDGES / 8) return;
#pragma unroll
    for (int h = 0; h < 2; ++h) {
        int   i  = t * 2 + h;
        int4   dv = ((const int4*)dst)[i];
        float4 wv = ((const float4*)w)[i];
        unsigned long long a0 = (1ULL << 32) | (unsigned)__float2uint_rn(wv.x * FIXS);
        unsigned long long a1 = (1ULL << 32) | (unsigned)__float2uint_rn(wv.y * FIXS);
        unsigned long long a2 = (1ULL << 32) | (unsigned)__float2uint_rn(wv.z * FIXS);
        unsigned long long a3 = (1ULL << 32) | (unsigned)__float2uint_rn(wv.w * FIXS);
        int p0 = (int)(atomicAdd(&g_pk[dv.x], a0) >> 32);
        int p1 = (int)(atomicAdd(&g_pk[dv.y], a1) >> 32);
        int p2 = (int)(atomicAdd(&g_pk[dv.z], a2) >> 32);
        int p3 = (int)(atomicAdd(&g_pk[dv.w], a3) >> 32);
        ((int4*)g_pos)[i] = make_int4(p0, p1, p2, p3);
    }
}

// unpack, rsqrt, bump-allocate; restore g_pk=0 for the next call
__global__ void k_alloc() {
    int i = blockIdx.x * blockDim.x + threadIdx.x;
    if (i >= N_NODES) return;
    unsigned long long pk = g_pk[i];
    g_pk[i] = 0ULL;
    int cnt = (int)(pk >> 32);
    float deg = 1.0f + (float)(unsigned)(pk & 0xFFFFFFFFULL) * FIXR;
    g_dis[i] = rsqrtf(deg);
    g_cnt[i] = cnt;
    g_row[i] = atomicAdd(&g_total, cnt);
}

// fill bins: 8 edges/thread; payload (src, raw w); one row[dst] gather each
__global__ void k_fill(const int* __restrict__ src,
                       const int* __restrict__ dst,
                       const float* __restrict__ w) {
    int t = blockIdx.x * blockDim.x + threadIdx.x;
    if (t >= N_EDGES / 8) return;
    int4   sv0 = ((const int4*)src)[t * 2],     sv1 = ((const int4*)src)[t * 2 + 1];
    int4   dv0 = ((const int4*)dst)[t * 2],     dv1 = ((const int4*)dst)[t * 2 + 1];
    int4   pv0 = ((const int4*)g_pos)[t * 2],   pv1 = ((const int4*)g_pos)[t * 2 + 1];
    float4 wv0 = ((const float4*)w)[t * 2],     wv1 = ((const float4*)w)[t * 2 + 1];
    int r0 = g_row[dv0.x], r1 = g_row[dv0.y], r2 = g_row[dv0.z], r3 = g_row[dv0.w];
    int r4 = g_row[dv1.x], r5 = g_row[dv1.y], r6 = g_row[dv1.z], r7 = g_row[dv1.w];
    g_bins[r0 + pv0.x] = make_int2(sv0.x, __float_as_int(wv0.x));
    g_bins[r1 + pv0.y] = make_int2(sv0.y, __float_as_int(wv0.y));
    g_bins[r2 + pv0.z] = make_int2(sv0.z, __float_as_int(wv0.z));
    g_bins[r3 + pv0.w] = make_int2(sv0.w, __float_as_int(wv0.w));
    g_bins[r4 + pv1.x] = make_int2(sv1.x, __float_as_int(wv1.x));
    g_bins[r5 + pv1.y] = make_int2(sv1.y, __float_as_int(wv1.y));
    g_bins[r6 + pv1.z] = make_int2(sv1.z, __float_as_int(wv1.z));
    g_bins[r7 + pv1.w] = make_int2(sv1.w, __float_as_int(wv1.w));
}

// ---------------------------------------------------------------------------
// dense 64x64 GEMM, f32x2 packed math, 2 rows/thread, fp16 output:
//   Hs[row] = half( dis[row] * (X[row] @ W) )
// ---------------------------------------------------------------------------
__global__ void __launch_bounds__(128) k_gemm(const float* __restrict__ X,
                                              const float* __restrict__ W,
                                              uint2* __restrict__ H) {
    __shared__ ulonglong2 WsU[1024];          // 64x64 floats = 16KB
    float* Ws = (float*)WsU;
    int tid = threadIdx.x;
    {
        const float4* W4 = (const float4*)W;
        float4* Ws4 = (float4*)Ws;
#pragma unroll
        for (int i = 0; i < 8; ++i) Ws4[tid + i * 128] = W4[tid + i * 128];
    }
    __syncthreads();

    int r0 = blockIdx.x * 256 + tid;
    int r1 = r0 + 128;
    bool has0 = (r0 < N_NODES), has1 = (r1 < N_NODES);
    if (!has0) return;

    float di0 = g_dis[r0];
    float di1 = has1 ? g_dis[r1] : 0.f;
    const float4* x0 = (const float4*)(X + (size_t)r0 * D);
    const float4* x1 = (const float4*)(X + (size_t)(has1 ? r1 : r0) * D);

#pragma unroll 1
    for (int jc = 0; jc < 4; ++jc) {            // 16 output channels per chunk
        unsigned long long a0[8], a1[8];
#pragma unroll
        for (int j = 0; j < 8; ++j) { a0[j] = 0ULL; a1[j] = 0ULL; }

#pragma unroll
        for (int k4 = 0; k4 < 16; ++k4) {
            float4 xv0 = x0[k4];
            float4 xv1 = x1[k4];
            float xs0[4] = {xv0.x, xv0.y, xv0.z, xv0.w};
            float xs1[4] = {xv1.x, xv1.y, xv1.z, xv1.w};
#pragma unroll
            for (int kk = 0; kk < 4; ++kk) {
                int k = k4 * 4 + kk;
                unsigned long long xb0 = bcast2(xs0[kk]);
                unsigned long long xb1 = bcast2(xs1[kk]);
                const ulonglong2* wrow =
                    (const ulonglong2*)(Ws + k * D + jc * 16);
#pragma unroll
                for (int q = 0; q < 4; ++q) {
                    ulonglong2 wp = wrow[q];     // LDS.128 = 2 packed pairs
                    fma2(a0[q * 2 + 0], wp.x, xb0);
                    fma2(a0[q * 2 + 1], wp.y, xb0);
                    fma2(a1[q * 2 + 0], wp.x, xb1);
                    fma2(a1[q * 2 + 1], wp.y, xb1);
                }
            }
        }
#pragma unroll
        for (int q = 0; q < 4; ++q) {
            float2 f0 = unpack2(a0[q * 2 + 0]);
            float2 f1 = unpack2(a0[q * 2 + 1]);
            __half2 h0 = __floats2half2_rn(f0.x * di0, f0.y * di0);
            __half2 h1 = __floats2half2_rn(f1.x * di0, f1.y * di0);
            H[(size_t)r0 * 16 + jc * 4 + q] =
                make_uint2(*(unsigned*)&h0, *(unsigned*)&h1);
        }
        if (has1) {
#pragma unroll
            for (int q = 0; q < 4; ++q) {
                float2 f0 = unpack2(a1[q * 2 + 0]);
                float2 f1 = unpack2(a1[q * 2 + 1]);
                __half2 h0 = __floats2half2_rn(f0.x * di1, f0.y * di1);
                __half2 h1 = __floats2half2_rn(f1.x * di1, f1.y * di1);
                H[(size_t)r1 * 16 + jc * 4 + q] =
                    make_uint2(*(unsigned*)&h0, *(unsigned*)&h1);
            }
        }
    }
}

// ---------------------------------------------------------------------------
// CSR aggregate: 16 lanes per node; lane owns 4 channels (uint2 = 2 half2).
// fp32 accumulation; fused self-loop, dis scale, ReLU. x8 unroll (MLP=8).
// ---------------------------------------------------------------------------
__device__ __forceinline__ void acc_h4(float4& acc, uint2 v, float nm) {
    float2 f0 = __half22float2(*(__half2*)&v.x);
    float2 f1 = __half22float2(*(__half2*)&v.y);
    acc.x = fmaf(nm, f0.x, acc.x); acc.y = fmaf(nm, f0.y, acc.y);
    acc.z = fmaf(nm, f1.x, acc.z); acc.w = fmaf(nm, f1.y, acc.w);
}

__global__ void __launch_bounds__(256) k_agg(const uint2* __restrict__ H,
                                             float* __restrict__ A) {
    int idx = blockIdx.x * 256 + threadIdx.x;
    int n = idx >> 4;
    if (n >= N_NODES) return;
    int l = idx & 15;

    int e   = g_row[n];
    int end = e + g_cnt[n];

    float4 acc;
    {   // self-loop term Hs[n]
        uint2 sv = H[(size_t)n * 16 + l];
        float2 f0 = __half22float2(*(__half2*)&sv.x);
        float2 f1 = __half22float2(*(__half2*)&sv.y);
        acc = make_float4(f0.x, f0.y, f1.x, f1.y);
    }

    for (; e + 8 <= end; e += 8) {
        int2 p[8];
#pragma unroll
        for (int j = 0; j < 8; ++j) p[j] = g_bins[e + j];
        uint2 v[8];
#pragma unroll
        for (int j = 0; j < 8; ++j) v[j] = H[(size_t)p[j].x * 16 + l];
#pragma unroll
        for (int j = 0; j < 8; ++j) acc_h4(acc, v[j], __int_as_float(p[j].y));
    }
    if (e + 4 <= end) {
        int2 p[4];
#pragma unroll
        for (int j = 0; j < 4; ++j) p[j] = g_bins[e + j];
        uint2 v[4];
#pragma unroll
        for (int j = 0; j < 4; ++j) v[j] = H[(size_t)p[j].x * 16 + l];
#pragma unroll
        for (int j = 0; j < 4; ++j) acc_h4(acc, v[j], __int_as_float(p[j].y));
        e += 4;
    }
    for (; e < end; ++e) {
        int2 p = g_bins[e];
        uint2 v = H[(size_t)p.x * 16 + l];
        acc_h4(acc, v, __int_as_float(p.y));
    }

    float di = g_dis[n];
    acc.x = fmaxf(acc.x * di, 0.f); acc.y = fmaxf(acc.y * di, 0.f);
    acc.z = fmaxf(acc.z * di, 0.f); acc.w = fmaxf(acc.w * di, 0.f);
    ((float4*)A)[(size_t)n * 16 + l] = acc;
}

// ---------------------------------------------------------------------------
extern "C" void kernel_launch(void* const* d_in, const int* in_sizes, int n_in,
                              void* d_out, int out_size) {
    const float* x   = (const float*)d_in[0];
    const int*   ei  = (const int*)d_in[1];     // int32 (JAX x64 disabled)
    const float* w   = (const float*)d_in[2];
    const float* W0  = (const float*)d_in[3];
    const float* W1  = (const float*)d_in[4];
    float* out = (float*)d_out;

    const int* src = ei;
    const int* dst = ei + N_EDGES;

    uint2* p_h;
    float* p_agg;
    cudaGetSymbolAddress((void**)&p_h, g_h);
    cudaGetSymbolAddress((void**)&p_agg, g_agg);

    const int TB = 256;
    int gN    = (N_NODES + TB - 1) / TB;
    int gE8   = (N_EDGES / 8 + TB - 1) / TB;
    int gAgg  = (N_NODES * 16 + TB - 1) / TB;
    int gGemm = (N_NODES + 255) / 256;          // 2 rows/thread, 128 thr

    // prep (g_pk zero-restore invariant; no init kernel)
    k_hist<<<gE8, TB>>>(dst, w);
    k_alloc<<<gN, TB>>>();
    k_fill<<<gE8, TB>>>(src, dst, w);

    // layer 1
    k_gemm<<<gGemm, 128>>>(x, W0, p_h);
    k_agg<<<gAgg, TB>>>(p_h, p_agg);

    // layer 2
    k_gemm<<<gGemm, 128>>>(p_agg, W1, p_h);
    k_agg<<<gAgg, TB>>>(p_h, out);
}